// round 11
// baseline (speedup 1.0000x reference)
#include <cuda_runtime.h>
#include <math.h>

#define NN   20000
#define BB   2
#define TT   12
#define FIN  9
#define HH   64
#define EE   200000
#define ROWS (BB*NN)   // 40000

#define L9_TILES   313    // 128 rows each
#define K1_TILES   313    // 128 rows each
#define Y9_TILES   157    // 256 rows each
#define XROWS      (BB * TT * NN)   // 480000
#define PREP_BLOCKS (XROWS / 256)   // 1875

// ---------------- scratch (device globals; no allocations allowed) ----------
__device__ int   g_cnt[NN];
__device__ int   g_fill[NN];
__device__ int   g_ptr[NN + 1];
__device__ float g_deginv[NN];
__device__ unsigned int g_ticket;
__device__ int2  g_csr_sw[EE];     // (src, float_as_int(w * deginv[dst]))
__device__ __align__(16) float g_y1all[(long)TT * ROWS * HH];
__device__ __align__(16) float g_t9pall[(long)TT * ROWS * 16];
__device__ __align__(16) float g_xr9all[(long)TT * ROWS * FIN];
__device__ __align__(16) float g_y9all[(long)TT * ROWS * 16];
__device__ __align__(16) float g_x16[(long)XROWS * 16];
__device__ float g_v[9];
__device__ float g_vc[BB];

// ---------------- helpers ----------------------------------------------------
__device__ __forceinline__ float elu_f(float v) { return v > 0.f ? v : expm1f(v); }

__device__ __forceinline__ void ffma2(unsigned long long& d,
                                      unsigned long long a, unsigned long long b) {
    asm("fma.rn.f32x2 %0, %1, %2, %0;" : "+l"(d) : "l"(a), "l"(b));
}
__device__ __forceinline__ float2 u2f2(unsigned long long u) {
    float2 r; asm("mov.b64 {%0, %1}, %2;" : "=f"(r.x), "=f"(r.y) : "l"(u)); return r;
}

// ---------------- prep+scan (last-block ticket) -------------------------------
__global__ void __launch_bounds__(256) prep_scan_kernel(
    const float* __restrict__ graph, const int* __restrict__ edst,
    const float* __restrict__ encW, const float* __restrict__ encb,
    const float* __restrict__ decW, const float* __restrict__ decb,
    const float* __restrict__ tev)
{
    int tid = threadIdx.x;
    int i = blockIdx.x * 256 + tid;
    if (i < XROWS) {
        float v[16];
        #pragma unroll
        for (int f = 0; f < 16; f++) v[f] = 0.f;
        const float* gp = graph + (long)i * 9;
        #pragma unroll
        for (int f = 0; f < 9; f++) v[f] = gp[f];
        float4* dst = (float4*)(g_x16 + (long)i * 16);
        dst[0] = make_float4(v[0], v[1], v[2], v[3]);
        dst[1] = make_float4(v[4], v[5], v[6], v[7]);
        dst[2] = make_float4(v[8], v[9], v[10], v[11]);
        dst[3] = make_float4(v[12], v[13], v[14], v[15]);
    }
    if (i < EE) atomicAdd(&g_cnt[edst[i]], 1);
    __threadfence();

    __shared__ unsigned int slast;
    if (tid == 0) slast = atomicAdd(&g_ticket, 1u);
    __syncthreads();
    if (slast != (unsigned)(gridDim.x - 1)) return;
    if (tid == 0) g_ticket = 0;

    __shared__ float sv[19];
    if (tid < 18) {
        float s = 0.f;
        for (int j = 0; j < 64; j++) s = fmaf(encW[tid * 64 + j], decW[j], s);
        sv[tid] = s;
    } else if (tid == 18) {
        float s = decb[0];
        for (int j = 0; j < 64; j++) s = fmaf(encb[j], decW[j], s);
        sv[18] = s;
    }
    __syncthreads();
    if (tid < 9) g_v[tid] = sv[tid];
    if (tid < BB) {
        float c = sv[18];
        #pragma unroll
        for (int f = 0; f < 9; f++) c = fmaf(tev[tid * 9 + f], sv[9 + f], c);
        g_vc[tid] = c;
    }

    __shared__ int wsum[8];
    __shared__ int carry;
    int lane = tid & 31, wid = tid >> 5;
    if (tid == 0) { carry = 0; g_ptr[0] = 0; }
    __syncthreads();
    for (int base = 0; base < NN; base += 256) {
        int idx = base + tid;
        int v = (idx < NN) ? __ldcg(&g_cnt[idx]) : 0;
        if (idx < NN) {
            g_deginv[idx] = 1.0f / fmaxf((float)v, 1.0f);
            g_cnt[idx] = 0;
            g_fill[idx] = 0;
        }
        int s = v;
        #pragma unroll
        for (int off = 1; off < 32; off <<= 1) {
            int tv = __shfl_up_sync(0xffffffffu, s, off);
            if (lane >= off) s += tv;
        }
        if (lane == 31) wsum[wid] = s;
        __syncthreads();
        if (wid == 0) {
            int ws = (lane < 8) ? wsum[lane] : 0;
            #pragma unroll
            for (int off = 1; off < 8; off <<= 1) {
                int tv = __shfl_up_sync(0xffffffffu, ws, off, 8);
                if ((lane & 7) >= off) ws += tv;
            }
            if (lane < 8) wsum[lane] = ws;
        }
        __syncthreads();
        int excl = wid ? wsum[wid - 1] : 0;
        if (idx < NN) g_ptr[idx + 1] = carry + excl + s;
        __syncthreads();
        if (tid == 0) carry += wsum[7];
        __syncthreads();
    }
}

__global__ void fill_kernel(const int* __restrict__ src, const int* __restrict__ dst,
                            const float* __restrict__ w) {
    int e = blockIdx.x * 256 + threadIdx.x;
    if (e < EE) {
        int d = dst[e];
        int pos = g_ptr[d] + atomicAdd(&g_fill[d], 1);
        g_csr_sw[pos] = make_int2(src[e], __float_as_int(w[e] * g_deginv[d]));
    }
}

// ============================================================================
// big_lin9: ALL timesteps of sage1. 128 rows/block, GEMM 4 rows x 8 cols.
// ============================================================================
__global__ void __launch_bounds__(256) big_lin9_kernel(
    const float* __restrict__ W1l, const float* __restrict__ W1r,
    const float* __restrict__ b1)
{
    __shared__ __align__(16) float sW9[18 * 64];
    __shared__ __align__(16) float sb9[64];
    __shared__ float sax9[128 * 33];

    int tid = threadIdx.x;
    int warp = tid >> 5, lane = tid & 31;
    int hh = lane >> 4, f16 = lane & 15;

    int t  = blockIdx.x / L9_TILES;
    int lb = blockIdx.x % L9_TILES;
    int row0 = lb * 128;

    const float* w1l = W1l + t * 576;
    const float* w1r = W1r + t * 576;
    for (int i = tid; i < 1152; i += 256)
        sW9[i] = (i < 576) ? w1l[i] : w1r[i - 576];
    if (tid < 64) sb9[tid] = b1[t * 64 + tid];

    // gather: half-warp covers 8 rows, ALL 8 in flight
    {
        int rbase = (warp * 2 + hh) * 8;
        float acc[8];
        const float* xb[8];
        int sA[8], eA[8], nn_[8];
        int maxlen = 0;
        #pragma unroll
        for (int i = 0; i < 8; i++) {
            int row = row0 + rbase + i;
            acc[i] = 0.f;
            if (row < ROWS) {
                int b = row / NN, n = row % NN;
                nn_[i] = n;
                xb[i] = g_x16 + ((long)b * TT + t) * NN * 16;
                sA[i] = g_ptr[n]; eA[i] = g_ptr[n + 1];
                int len = eA[i] - sA[i];
                maxlen = len > maxlen ? len : maxlen;
            } else { nn_[i] = -1; xb[i] = g_x16; sA[i] = 0; eA[i] = 0; }
        }
        for (int k = 0; k < maxlen; k++) {
            #pragma unroll
            for (int i = 0; i < 8; i++) {
                int j = sA[i] + k;
                if (j < eA[i]) {
                    int2 sw = g_csr_sw[j];
                    acc[i] = fmaf(__int_as_float(sw.y),
                                  xb[i][(long)sw.x * 16 + f16], acc[i]);
                }
            }
        }
        #pragma unroll
        for (int i = 0; i < 8; i++) {
            if (nn_[i] >= 0) {
                int rr = rbase + i;
                sax9[rr * 33 + f16] = acc[i];
                sax9[rr * 33 + 16 + f16] = xb[i][(long)nn_[i] * 16 + f16];
            }
        }
    }
    __syncthreads();

    int cx = tid & 7, ry = tid >> 3;
    int f0 = cx * 8, r0 = ry * 4;
    float4 accA[4], accB[4];
    {
        float4 bA = *(const float4*)&sb9[f0];
        float4 bB = *(const float4*)&sb9[f0 + 4];
        #pragma unroll
        for (int i = 0; i < 4; i++) { accA[i] = bA; accB[i] = bB; }
    }
    #pragma unroll
    for (int k = 0; k < 18; k++) {
        float4 w0 = *(const float4*)&sW9[k * 64 + f0];
        float4 w1 = *(const float4*)&sW9[k * 64 + f0 + 4];
        int ko = (k < 9) ? k : (k + 7);
        #pragma unroll
        for (int i = 0; i < 4; i++) {
            float a = sax9[(r0 + i) * 33 + ko];
            accA[i].x = fmaf(a, w0.x, accA[i].x);
            accA[i].y = fmaf(a, w0.y, accA[i].y);
            accA[i].z = fmaf(a, w0.z, accA[i].z);
            accA[i].w = fmaf(a, w0.w, accA[i].w);
            accB[i].x = fmaf(a, w1.x, accB[i].x);
            accB[i].y = fmaf(a, w1.y, accB[i].y);
            accB[i].z = fmaf(a, w1.z, accB[i].z);
            accB[i].w = fmaf(a, w1.w, accB[i].w);
        }
    }
    float* ybase = g_y1all + (long)t * ROWS * 64;
    #pragma unroll
    for (int i = 0; i < 4; i++) {
        int row = row0 + r0 + i;
        if (row < ROWS) {
            float4 vA = accA[i], vB = accB[i];
            vA.x = elu_f(vA.x); vA.y = elu_f(vA.y); vA.z = elu_f(vA.z); vA.w = elu_f(vA.w);
            vB.x = elu_f(vB.x); vB.y = elu_f(vB.y); vB.z = elu_f(vB.z); vB.w = elu_f(vB.w);
            *(float4*)(ybase + (long)row * 64 + f0) = vA;
            *(float4*)(ybase + (long)row * 64 + f0 + 4) = vB;
        }
    }
}

// ============================================================================
// big_lin64 (fused, R9 structure): gather agg(d=64) of y1 (8 rows in flight)
//  + [agg|x]@[W2l;W2r] (K=128, ffma2 8x4) + bias + elu
//  + epilogue t9p = y2@W3l (padded), xr9 = y2@W3r.
// ============================================================================
#define SAX_STRIDE 132
#define SM64_FLOATS (8192 + 1152 + 64 + 128 * SAX_STRIDE)
#define SM64_BYTES  (SM64_FLOATS * 4)

__global__ void __launch_bounds__(256) big_lin64_kernel(
    const float* __restrict__ W2l_, const float* __restrict__ W2r_,
    const float* __restrict__ b2_,
    const float* __restrict__ W3l_, const float* __restrict__ W3r_)
{
    extern __shared__ __align__(16) float sm[];
    float* sW2 = sm;                 // [64 k-pairs][64 f][2]
    float* sW3 = sW2 + 8192;         // [2 m][32 k-pairs][9 f][2]
    float* sb  = sW3 + 1152;         // [64]
    float* sax = sb + 64;            // [128][132]: 0..63 agg | 64..127 x

    int t    = blockIdx.x / K1_TILES;
    int tile = blockIdx.x % K1_TILES;
    const float* W2l = W2l_ + t * 4096;
    const float* W2r = W2r_ + t * 4096;
    const float* b2  = b2_  + t * 64;
    const float* W3l = W3l_ + t * 576;
    const float* W3r = W3r_ + t * 576;

    int tid = threadIdx.x;
    for (int i = tid; i < 8192; i += 256) {
        int f = i & 63, kk = i >> 6;
        float v = (kk < 64) ? W2l[kk * 64 + f] : W2r[(kk - 64) * 64 + f];
        sW2[((kk >> 1) * 64 + f) * 2 + (kk & 1)] = v;
    }
    for (int i = tid; i < 1152; i += 256) {
        int m = (i >= 576);
        int rem = i - m * 576;
        int kk = rem / 9, f = rem % 9;
        float v = m ? W3r[kk * 9 + f] : W3l[kk * 9 + f];
        sW3[m * 576 + ((kk >> 1) * 9 + f) * 2 + (kk & 1)] = v;
    }
    if (tid < 64) sb[tid] = b2[tid];

    int row0 = tile * 128;
    int warp = tid >> 5, lane = tid & 31;
    const float* ytbase = g_y1all + (long)t * ROWS * 64;

    // gather: 8 rows in flight per warp, lane owns 2 features (MLP ~16)
    #pragma unroll 1
    for (int pass = 0; pass < 2; pass++) {
        int rbase = warp * 16 + pass * 8;
        float2 acc[8];
        const float* yb[8];
        int sA[8], eA[8], nn_[8];
        int maxlen = 0;
        #pragma unroll
        for (int i = 0; i < 8; i++) {
            int row = row0 + rbase + i;
            acc[i] = make_float2(0.f, 0.f);
            if (row < ROWS) {
                int b = row / NN, n = row % NN;
                nn_[i] = n;
                yb[i] = ytbase + (long)b * NN * 64;
                sA[i] = g_ptr[n]; eA[i] = g_ptr[n + 1];
                int len = eA[i] - sA[i];
                maxlen = len > maxlen ? len : maxlen;
            } else { nn_[i] = -1; yb[i] = ytbase; sA[i] = 0; eA[i] = 0; }
        }
        for (int k = 0; k < maxlen; k++) {
            #pragma unroll
            for (int i = 0; i < 8; i++) {
                int j = sA[i] + k;
                if (j < eA[i]) {
                    int2 sw = g_csr_sw[j];
                    float2 v = *(const float2*)(yb[i] + (long)sw.x * 64 + lane * 2);
                    float wt = __int_as_float(sw.y);
                    acc[i].x = fmaf(wt, v.x, acc[i].x);
                    acc[i].y = fmaf(wt, v.y, acc[i].y);
                }
            }
        }
        #pragma unroll
        for (int i = 0; i < 8; i++) {
            if (nn_[i] >= 0) {
                int rr = rbase + i;
                *(float2*)(sax + rr * SAX_STRIDE + lane * 2) = acc[i];
                *(float2*)(sax + rr * SAX_STRIDE + 64 + lane * 2) =
                    *(const float2*)(yb[i] + (long)nn_[i] * 64 + lane * 2);
            }
        }
    }
    __syncthreads();

    // GEMM: 8 rows x 4 cols per thread, K=128 as 64 f32x2 pairs
    int tx = tid & 15, ty = tid >> 4;
    int f0 = tx * 4, r0 = ty * 8;
    unsigned long long acc2[8][4];
    #pragma unroll
    for (int i = 0; i < 8; i++)
        #pragma unroll
        for (int j = 0; j < 4; j++) acc2[i][j] = 0ull;

    const unsigned long long* w2 = (const unsigned long long*)sW2;
    #pragma unroll 2
    for (int k2 = 0; k2 < 64; k2++) {
        const unsigned long long* wp = w2 + (k2 * 64 + f0);
        ulonglong2 wa = *(const ulonglong2*)(wp);
        ulonglong2 wb = *(const ulonglong2*)(wp + 2);
        #pragma unroll
        for (int i = 0; i < 8; i++) {
            unsigned long long a2 =
                *(const unsigned long long*)(sax + (r0 + i) * SAX_STRIDE + 2 * k2);
            ffma2(acc2[i][0], a2, wa.x);
            ffma2(acc2[i][1], a2, wa.y);
            ffma2(acc2[i][2], a2, wb.x);
            ffma2(acc2[i][3], a2, wb.y);
        }
    }
    __syncthreads();

    #pragma unroll
    for (int i = 0; i < 8; i++) {
        float4 v;
        float2 p0 = u2f2(acc2[i][0]);
        float2 p1 = u2f2(acc2[i][1]);
        float2 p2 = u2f2(acc2[i][2]);
        float2 p3 = u2f2(acc2[i][3]);
        v.x = elu_f(p0.x + p0.y + sb[f0 + 0]);
        v.y = elu_f(p1.x + p1.y + sb[f0 + 1]);
        v.z = elu_f(p2.x + p2.y + sb[f0 + 2]);
        v.w = elu_f(p3.x + p3.y + sb[f0 + 3]);
        *(float4*)(sax + (r0 + i) * SAX_STRIDE + f0) = v;
    }
    __syncthreads();

    // epilogue: t9p = y2@W3l (padded rows), xr9 = y2@W3r
    {
        int err2 = tid & 127;
        int m = tid >> 7;
        int grow = row0 + err2;
        const float* yrow = sax + err2 * SAX_STRIDE;
        const unsigned long long* w3p = (const unsigned long long*)sW3 + m * 288;
        unsigned long long o2[9];
        #pragma unroll
        for (int f = 0; f < 9; f++) o2[f] = 0ull;
        #pragma unroll 4
        for (int k2 = 0; k2 < 32; k2++) {
            unsigned long long y2p = *(const unsigned long long*)(yrow + 2 * k2);
            const unsigned long long* wk = w3p + k2 * 9;
            #pragma unroll
            for (int f = 0; f < 9; f++) ffma2(o2[f], y2p, wk[f]);
        }
        if (grow < ROWS) {
            float* dst = m ? (g_xr9all + ((long)t * ROWS + grow) * 9)
                           : (g_t9pall + ((long)t * ROWS + grow) * 16);
            #pragma unroll
            for (int f = 0; f < 9; f++) { float2 p = u2f2(o2[f]); dst[f] = p.x + p.y; }
        }
    }
}

// ============================================================================
// y9: ALL timesteps of sage3 aggregation + elu.
// ============================================================================
__global__ void __launch_bounds__(256) y9_kernel(const float* __restrict__ b3)
{
    int tid = threadIdx.x;
    int warp = tid >> 5, lane = tid & 31;
    int hh = lane >> 4, f16 = lane & 15;

    int t    = blockIdx.x / Y9_TILES;
    int tile = blockIdx.x % Y9_TILES;
    int row0 = tile * 256;

    float b3v = (f16 < 9) ? b3[t * 9 + f16] : 0.f;
    const float* tball = g_t9pall + (long)t * ROWS * 16;
    const float* xrall = g_xr9all + (long)t * ROWS * 9;
    float* y9t = g_y9all + (long)t * ROWS * 16;

    #pragma unroll 1
    for (int pass = 0; pass < 2; pass++) {
        int rbase = warp * 32 + hh * 16 + pass * 8;
        float acc[8];
        const float* tb[8];
        int sA[8], eA[8], nn_[8];
        int maxlen = 0;
        #pragma unroll
        for (int i = 0; i < 8; i++) {
            int row = row0 + rbase + i;
            acc[i] = 0.f;
            if (row < ROWS) {
                int b = row / NN, n = row % NN;
                nn_[i] = n;
                tb[i] = tball + (long)b * NN * 16;
                sA[i] = g_ptr[n]; eA[i] = g_ptr[n + 1];
                int len = eA[i] - sA[i];
                maxlen = len > maxlen ? len : maxlen;
            } else { nn_[i] = -1; tb[i] = tball; sA[i] = 0; eA[i] = 0; }
        }
        for (int k = 0; k < maxlen; k++) {
            #pragma unroll
            for (int i = 0; i < 8; i++) {
                int j = sA[i] + k;
                if (j < eA[i]) {
                    int2 sw = g_csr_sw[j];
                    acc[i] = fmaf(__int_as_float(sw.y),
                                  tb[i][(long)sw.x * 16 + f16], acc[i]);
                }
            }
        }
        #pragma unroll
        for (int i = 0; i < 8; i++) {
            if (nn_[i] >= 0) {
                int row = row0 + rbase + i;
                float val = 0.f;
                if (f16 < 9)
                    val = elu_f(acc[i] + xrall[(long)row * 9 + f16] + b3v);
                y9t[(long)row * 16 + f16] = val;
            }
        }
    }
}

// ============================================================================
// gru_all: all 12 GRU steps; h in registers; writes collapsed output.
// ============================================================================
__global__ void __launch_bounds__(256) gru_all_kernel(
    const float* __restrict__ Wih, const float* __restrict__ Whh,
    const float* __restrict__ bih, const float* __restrict__ bhh,
    float* __restrict__ out)
{
    __shared__ float swih[TT * 243], swhh[TT * 243];
    __shared__ float sbi[TT * 27], sbh[TT * 27];
    __shared__ float sv9[9], svc[BB];

    int tid = threadIdx.x;
    for (int i = tid; i < TT * 243; i += 256) { swih[i] = Wih[i]; swhh[i] = Whh[i]; }
    for (int i = tid; i < TT * 27; i += 256) { sbi[i] = bih[i]; sbh[i] = bhh[i]; }
    if (tid < 9) sv9[tid] = g_v[tid];
    if (tid < BB) svc[tid] = g_vc[tid];
    __syncthreads();

    int idx = blockIdx.x * 256 + tid;
    if (idx >= ROWS) return;
    int b = idx / NN, n = idx % NN;

    float h[9];
    #pragma unroll
    for (int f = 0; f < 9; f++) h[f] = 0.f;

    #pragma unroll 1
    for (int t = 0; t < TT; t++) {
        const float* yp = g_y9all + ((long)t * ROWS + idx) * 16;
        float y[9];
        float4 y0 = *(const float4*)yp;
        float4 y1 = *(const float4*)(yp + 4);
        y[0] = y0.x; y[1] = y0.y; y[2] = y0.z; y[3] = y0.w;
        y[4] = y1.x; y[5] = y1.y; y[6] = y1.z; y[7] = y1.w;
        y[8] = yp[8];

        const float* wiT = swih + t * 243;
        const float* whT = swhh + t * 243;
        const float* biT = sbi + t * 27;
        const float* bhT = sbh + t * 27;

        float gs[18], gin[9], ghn[9];
        #pragma unroll
        for (int j = 0; j < 18; j++) gs[j] = biT[j] + bhT[j];
        #pragma unroll
        for (int j = 0; j < 9; j++) { gin[j] = biT[18 + j]; ghn[j] = bhT[18 + j]; }
        #pragma unroll
        for (int k = 0; k < 9; k++) {
            float yk = y[k], hk = h[k];
            const float* wi = wiT + k * 27;
            const float* wh = whT + k * 27;
            #pragma unroll
            for (int j = 0; j < 18; j++) gs[j] = fmaf(yk, wi[j], fmaf(hk, wh[j], gs[j]));
            #pragma unroll
            for (int j = 0; j < 9; j++) {
                gin[j] = fmaf(yk, wi[18 + j], gin[j]);
                ghn[j] = fmaf(hk, wh[18 + j], ghn[j]);
            }
        }

        long iout = ((long)b * TT + t) * NN + n;
        float dot = svc[b];
        #pragma unroll
        for (int f = 0; f < 9; f++) {
            float r  = 1.f / (1.f + expf(-gs[f]));
            float z  = 1.f / (1.f + expf(-gs[9 + f]));
            float nv = tanhf(gin[f] + r * ghn[f]);
            float hv = (1.f - z) * nv + z * h[f];
            h[f] = hv;
            dot = fmaf(hv, sv9[f], dot);
        }
        float mask = g_x16[iout * 16];
        out[iout] = (mask != 0.f) ? dot : 0.f;
    }
}

// ---------------- host ------------------------------------------------------
extern "C" void kernel_launch(void* const* d_in, const int* in_sizes, int n_in,
                              void* d_out, int out_size) {
    const float* graph = (const float*)d_in[0];
    const float* tev   = (const float*)d_in[1];
    const float* ew    = (const float*)d_in[3];
    const int*   esrc  = (const int*)d_in[4];
    const int*   edst  = (const int*)d_in[5];
    const float* W1l = (const float*)d_in[6];
    const float* b1  = (const float*)d_in[7];
    const float* W1r = (const float*)d_in[8];
    const float* W2l = (const float*)d_in[9];
    const float* b2  = (const float*)d_in[10];
    const float* W2r = (const float*)d_in[11];
    const float* W3l = (const float*)d_in[12];
    const float* b3  = (const float*)d_in[13];
    const float* W3r = (const float*)d_in[14];
    const float* Wih = (const float*)d_in[15];
    const float* Whh = (const float*)d_in[16];
    const float* bih = (const float*)d_in[17];
    const float* bhh = (const float*)d_in[18];
    const float* encW = (const float*)d_in[19];
    const float* encb = (const float*)d_in[20];
    const float* decW = (const float*)d_in[21];
    const float* decb = (const float*)d_in[22];
    float* out = (float*)d_out;

    cudaFuncSetAttribute(big_lin64_kernel,
                         cudaFuncAttributeMaxDynamicSharedMemorySize, SM64_BYTES);

    prep_scan_kernel<<<PREP_BLOCKS, 256>>>(graph, edst, encW, encb, decW, decb, tev);
    fill_kernel<<<(EE + 255) / 256, 256>>>(esrc, edst, ew);
    big_lin9_kernel<<<TT * L9_TILES, 256>>>(W1l, W1r, b1);
    big_lin64_kernel<<<TT * K1_TILES, 256, SM64_BYTES>>>(W2l, W2r, b2, W3l, W3r);
    y9_kernel<<<TT * Y9_TILES, 256>>>(b3);
    gru_all_kernel<<<(ROWS + 255) / 256, 256>>>(Wih, Whh, bih, bhh, out);
}

// round 12
// speedup vs baseline: 1.1439x; 1.1439x over previous
#include <cuda_runtime.h>
#include <math.h>

#define NN   20000
#define BB   2
#define TT   12
#define FIN  9
#define HH   64
#define EE   200000
#define ROWS (BB*NN)   // 40000

#define L9_TILES   313    // 128 rows each
#define K1_TILES   313    // 128 rows each
#define Y9_TILES   157    // 256 rows each
#define XROWS      (BB * TT * NN)   // 480000
#define PREP_BLOCKS (XROWS / 256)   // 1875

// ---------------- scratch (device globals; no allocations allowed) ----------
__device__ int   g_cnt[NN];
__device__ int   g_fill[NN];
__device__ int   g_ptr[NN + 1];
__device__ float g_deginv[NN];
__device__ unsigned int g_ticket;
__device__ int2  g_csr_sw[EE];     // (src*64 [byte off of 64B rows], f2i(w*deginv))
__device__ __align__(16) float g_y1all[(long)TT * ROWS * HH];
__device__ __align__(16) float g_t9pall[(long)TT * ROWS * 16];
__device__ __align__(16) float g_xr9all[(long)TT * ROWS * FIN];
__device__ __align__(16) float g_y9all[(long)TT * ROWS * 16];
__device__ __align__(16) float g_x16[(long)XROWS * 16];
__device__ float g_v[9];
__device__ float g_vc[BB];

// ---------------- helpers ----------------------------------------------------
__device__ __forceinline__ float elu_f(float v) { return v > 0.f ? v : expm1f(v); }

__device__ __forceinline__ void ffma2(unsigned long long& d,
                                      unsigned long long a, unsigned long long b) {
    asm("fma.rn.f32x2 %0, %1, %2, %0;" : "+l"(d) : "l"(a), "l"(b));
}
__device__ __forceinline__ float2 u2f2(unsigned long long u) {
    float2 r; asm("mov.b64 {%0, %1}, %2;" : "=f"(r.x), "=f"(r.y) : "l"(u)); return r;
}

// ---------------- prep+scan (last-block ticket) -------------------------------
__global__ void __launch_bounds__(256) prep_scan_kernel(
    const float* __restrict__ graph, const int* __restrict__ edst,
    const float* __restrict__ encW, const float* __restrict__ encb,
    const float* __restrict__ decW, const float* __restrict__ decb,
    const float* __restrict__ tev)
{
    int tid = threadIdx.x;
    int i = blockIdx.x * 256 + tid;
    if (i < XROWS) {
        float v[16];
        #pragma unroll
        for (int f = 0; f < 16; f++) v[f] = 0.f;
        const float* gp = graph + (long)i * 9;
        #pragma unroll
        for (int f = 0; f < 9; f++) v[f] = gp[f];
        float4* dst = (float4*)(g_x16 + (long)i * 16);
        dst[0] = make_float4(v[0], v[1], v[2], v[3]);
        dst[1] = make_float4(v[4], v[5], v[6], v[7]);
        dst[2] = make_float4(v[8], v[9], v[10], v[11]);
        dst[3] = make_float4(v[12], v[13], v[14], v[15]);
    }
    if (i < EE) atomicAdd(&g_cnt[edst[i]], 1);
    __threadfence();

    __shared__ unsigned int slast;
    if (tid == 0) slast = atomicAdd(&g_ticket, 1u);
    __syncthreads();
    if (slast != (unsigned)(gridDim.x - 1)) return;
    if (tid == 0) g_ticket = 0;

    __shared__ float sv[19];
    if (tid < 18) {
        float s = 0.f;
        for (int j = 0; j < 64; j++) s = fmaf(encW[tid * 64 + j], decW[j], s);
        sv[tid] = s;
    } else if (tid == 18) {
        float s = decb[0];
        for (int j = 0; j < 64; j++) s = fmaf(encb[j], decW[j], s);
        sv[18] = s;
    }
    __syncthreads();
    if (tid < 9) g_v[tid] = sv[tid];
    if (tid < BB) {
        float c = sv[18];
        #pragma unroll
        for (int f = 0; f < 9; f++) c = fmaf(tev[tid * 9 + f], sv[9 + f], c);
        g_vc[tid] = c;
    }

    __shared__ int wsum[8];
    __shared__ int carry;
    int lane = tid & 31, wid = tid >> 5;
    if (tid == 0) { carry = 0; g_ptr[0] = 0; }
    __syncthreads();
    for (int base = 0; base < NN; base += 256) {
        int idx = base + tid;
        int v = (idx < NN) ? __ldcg(&g_cnt[idx]) : 0;
        if (idx < NN) {
            g_deginv[idx] = 1.0f / fmaxf((float)v, 1.0f);
            g_cnt[idx] = 0;
            g_fill[idx] = 0;
        }
        int s = v;
        #pragma unroll
        for (int off = 1; off < 32; off <<= 1) {
            int tv = __shfl_up_sync(0xffffffffu, s, off);
            if (lane >= off) s += tv;
        }
        if (lane == 31) wsum[wid] = s;
        __syncthreads();
        if (wid == 0) {
            int ws = (lane < 8) ? wsum[lane] : 0;
            #pragma unroll
            for (int off = 1; off < 8; off <<= 1) {
                int tv = __shfl_up_sync(0xffffffffu, ws, off, 8);
                if ((lane & 7) >= off) ws += tv;
            }
            if (lane < 8) wsum[lane] = ws;
        }
        __syncthreads();
        int excl = wid ? wsum[wid - 1] : 0;
        if (idx < NN) g_ptr[idx + 1] = carry + excl + s;
        __syncthreads();
        if (tid == 0) carry += wsum[7];
        __syncthreads();
    }
}

__global__ void fill_kernel(const int* __restrict__ src, const int* __restrict__ dst,
                            const float* __restrict__ w) {
    int e = blockIdx.x * 256 + threadIdx.x;
    if (e < EE) {
        int d = dst[e];
        int pos = g_ptr[d] + atomicAdd(&g_fill[d], 1);
        // store byte offset for 64B rows (16 floats); 256B-row consumers shift <<2
        g_csr_sw[pos] = make_int2(src[e] << 6, __float_as_int(w[e] * g_deginv[d]));
    }
}

// ============================================================================
// big_lin9: ALL timesteps of sage1. 128 rows/block, GEMM 4 rows x 8 cols.
// ============================================================================
__global__ void __launch_bounds__(256) big_lin9_kernel(
    const float* __restrict__ W1l, const float* __restrict__ W1r,
    const float* __restrict__ b1)
{
    __shared__ __align__(16) float sW9[18 * 64];
    __shared__ __align__(16) float sb9[64];
    __shared__ float sax9[128 * 33];

    int tid = threadIdx.x;
    int warp = tid >> 5, lane = tid & 31;
    int hh = lane >> 4, f16 = lane & 15;
    int fb = f16 * 4;                      // byte offset of owned feature

    int t  = blockIdx.x / L9_TILES;
    int lb = blockIdx.x % L9_TILES;
    int row0 = lb * 128;

    const float* w1l = W1l + t * 576;
    const float* w1r = W1r + t * 576;
    for (int i = tid; i < 1152; i += 256)
        sW9[i] = (i < 576) ? w1l[i] : w1r[i - 576];
    if (tid < 64) sb9[tid] = b1[t * 64 + tid];

    // gather: half-warp covers 8 rows; 2 passes of 4 rows in flight
    #pragma unroll 1
    for (int pass = 0; pass < 2; pass++) {
        int rbase = (warp * 2 + hh) * 8 + pass * 4;
        float acc[4];
        const char* xb[4];
        int sA[4], eA[4], nn_[4];
        int maxlen = 0;
        #pragma unroll
        for (int i = 0; i < 4; i++) {
            int row = row0 + rbase + i;
            acc[i] = 0.f;
            if (row < ROWS) {
                int b = row / NN, n = row % NN;
                nn_[i] = n;
                xb[i] = (const char*)(g_x16 + ((long)b * TT + t) * NN * 16);
                sA[i] = g_ptr[n]; eA[i] = g_ptr[n + 1];
                int len = eA[i] - sA[i];
                maxlen = len > maxlen ? len : maxlen;
            } else { nn_[i] = -1; xb[i] = (const char*)g_x16; sA[i] = 0; eA[i] = 0; }
        }
        for (int k = 0; k < maxlen; k++) {
            #pragma unroll
            for (int i = 0; i < 4; i++) {
                int j = sA[i] + k;
                if (j < eA[i]) {
                    int2 sw = g_csr_sw[j];
                    float v = *(const float*)(xb[i] + sw.x + fb);
                    acc[i] = fmaf(__int_as_float(sw.y), v, acc[i]);
                }
            }
        }
        #pragma unroll
        for (int i = 0; i < 4; i++) {
            if (nn_[i] >= 0) {
                int rr = rbase + i;
                sax9[rr * 33 + f16] = acc[i];
                sax9[rr * 33 + 16 + f16] =
                    *(const float*)(xb[i] + ((long)nn_[i] << 6) + fb);
            }
        }
    }
    __syncthreads();

    int cx = tid & 7, ry = tid >> 3;
    int f0 = cx * 8, r0 = ry * 4;
    float4 accA[4], accB[4];
    {
        float4 bA = *(const float4*)&sb9[f0];
        float4 bB = *(const float4*)&sb9[f0 + 4];
        #pragma unroll
        for (int i = 0; i < 4; i++) { accA[i] = bA; accB[i] = bB; }
    }
    #pragma unroll
    for (int k = 0; k < 18; k++) {
        float4 w0 = *(const float4*)&sW9[k * 64 + f0];
        float4 w1 = *(const float4*)&sW9[k * 64 + f0 + 4];
        int ko = (k < 9) ? k : (k + 7);
        #pragma unroll
        for (int i = 0; i < 4; i++) {
            float a = sax9[(r0 + i) * 33 + ko];
            accA[i].x = fmaf(a, w0.x, accA[i].x);
            accA[i].y = fmaf(a, w0.y, accA[i].y);
            accA[i].z = fmaf(a, w0.z, accA[i].z);
            accA[i].w = fmaf(a, w0.w, accA[i].w);
            accB[i].x = fmaf(a, w1.x, accB[i].x);
            accB[i].y = fmaf(a, w1.y, accB[i].y);
            accB[i].z = fmaf(a, w1.z, accB[i].z);
            accB[i].w = fmaf(a, w1.w, accB[i].w);
        }
    }
    float* ybase = g_y1all + (long)t * ROWS * 64;
    #pragma unroll
    for (int i = 0; i < 4; i++) {
        int row = row0 + r0 + i;
        if (row < ROWS) {
            float4 vA = accA[i], vB = accB[i];
            vA.x = elu_f(vA.x); vA.y = elu_f(vA.y); vA.z = elu_f(vA.z); vA.w = elu_f(vA.w);
            vB.x = elu_f(vB.x); vB.y = elu_f(vB.y); vB.z = elu_f(vB.z); vB.w = elu_f(vB.w);
            *(float4*)(ybase + (long)row * 64 + f0) = vA;
            *(float4*)(ybase + (long)row * 64 + f0 + 4) = vB;
        }
    }
}

// ============================================================================
// big_lin64 (fused R9): gather agg(d=64) of y1 (4 rows in flight)
//  + [agg|x]@[W2l;W2r] (K=128, ffma2 8x4) + bias + elu
//  + epilogue t9p = y2@W3l (padded), xr9 = y2@W3r.
// ============================================================================
#define SAX_STRIDE 132
#define SM64_FLOATS (8192 + 1152 + 64 + 128 * SAX_STRIDE)
#define SM64_BYTES  (SM64_FLOATS * 4)

__global__ void __launch_bounds__(256) big_lin64_kernel(
    const float* __restrict__ W2l_, const float* __restrict__ W2r_,
    const float* __restrict__ b2_,
    const float* __restrict__ W3l_, const float* __restrict__ W3r_)
{
    extern __shared__ __align__(16) float sm[];
    float* sW2 = sm;                 // [64 k-pairs][64 f][2]
    float* sW3 = sW2 + 8192;         // [2 m][32 k-pairs][9 f][2]
    float* sb  = sW3 + 1152;         // [64]
    float* sax = sb + 64;            // [128][132]: 0..63 agg | 64..127 x

    int t    = blockIdx.x / K1_TILES;
    int tile = blockIdx.x % K1_TILES;
    const float* W2l = W2l_ + t * 4096;
    const float* W2r = W2r_ + t * 4096;
    const float* b2  = b2_  + t * 64;
    const float* W3l = W3l_ + t * 576;
    const float* W3r = W3r_ + t * 576;

    int tid = threadIdx.x;
    for (int i = tid; i < 8192; i += 256) {
        int f = i & 63, kk = i >> 6;
        float v = (kk < 64) ? W2l[kk * 64 + f] : W2r[(kk - 64) * 64 + f];
        sW2[((kk >> 1) * 64 + f) * 2 + (kk & 1)] = v;
    }
    for (int i = tid; i < 1152; i += 256) {
        int m = (i >= 576);
        int rem = i - m * 576;
        int kk = rem / 9, f = rem % 9;
        float v = m ? W3r[kk * 9 + f] : W3l[kk * 9 + f];
        sW3[m * 576 + ((kk >> 1) * 9 + f) * 2 + (kk & 1)] = v;
    }
    if (tid < 64) sb[tid] = b2[tid];

    int row0 = tile * 128;
    int warp = tid >> 5, lane = tid & 31;
    int lb2 = lane * 8;                    // byte offset of owned float2
    const char* ytbase = (const char*)(g_y1all + (long)t * ROWS * 64);

    // gather: 4 rows in flight per warp, lane owns 2 features
    #pragma unroll 1
    for (int pass = 0; pass < 4; pass++) {
        int rbase = warp * 16 + pass * 4;
        float2 acc[4];
        const char* yb[4];
        int sA[4], eA[4], nn_[4];
        int maxlen = 0;
        #pragma unroll
        for (int i = 0; i < 4; i++) {
            int row = row0 + rbase + i;
            acc[i] = make_float2(0.f, 0.f);
            if (row < ROWS) {
                int b = row / NN, n = row % NN;
                nn_[i] = n;
                yb[i] = ytbase + (long)b * NN * 256;
                sA[i] = g_ptr[n]; eA[i] = g_ptr[n + 1];
                int len = eA[i] - sA[i];
                maxlen = len > maxlen ? len : maxlen;
            } else { nn_[i] = -1; yb[i] = ytbase; sA[i] = 0; eA[i] = 0; }
        }
        for (int k = 0; k < maxlen; k++) {
            #pragma unroll
            for (int i = 0; i < 4; i++) {
                int j = sA[i] + k;
                if (j < eA[i]) {
                    int2 sw = g_csr_sw[j];
                    float2 v = *(const float2*)(yb[i] + ((long)sw.x << 2) + lb2);
                    float wt = __int_as_float(sw.y);
                    acc[i].x = fmaf(wt, v.x, acc[i].x);
                    acc[i].y = fmaf(wt, v.y, acc[i].y);
                }
            }
        }
        #pragma unroll
        for (int i = 0; i < 4; i++) {
            if (nn_[i] >= 0) {
                int rr = rbase + i;
                *(float2*)(sax + rr * SAX_STRIDE + lane * 2) = acc[i];
                *(float2*)(sax + rr * SAX_STRIDE + 64 + lane * 2) =
                    *(const float2*)(yb[i] + ((long)nn_[i] << 8) + lb2);
            }
        }
    }
    __syncthreads();

    // GEMM: 8 rows x 4 cols per thread, K=128 as 64 f32x2 pairs
    int tx = tid & 15, ty = tid >> 4;
    int f0 = tx * 4, r0 = ty * 8;
    unsigned long long acc2[8][4];
    #pragma unroll
    for (int i = 0; i < 8; i++)
        #pragma unroll
        for (int j = 0; j < 4; j++) acc2[i][j] = 0ull;

    const unsigned long long* w2 = (const unsigned long long*)sW2;
    #pragma unroll 2
    for (int k2 = 0; k2 < 64; k2++) {
        const unsigned long long* wp = w2 + (k2 * 64 + f0);
        ulonglong2 wa = *(const ulonglong2*)(wp);
        ulonglong2 wb = *(const ulonglong2*)(wp + 2);
        #pragma unroll
        for (int i = 0; i < 8; i++) {
            unsigned long long a2 =
                *(const unsigned long long*)(sax + (r0 + i) * SAX_STRIDE + 2 * k2);
            ffma2(acc2[i][0], a2, wa.x);
            ffma2(acc2[i][1], a2, wa.y);
            ffma2(acc2[i][2], a2, wb.x);
            ffma2(acc2[i][3], a2, wb.y);
        }
    }
    __syncthreads();

    #pragma unroll
    for (int i = 0; i < 8; i++) {
        float4 v;
        float2 p0 = u2f2(acc2[i][0]);
        float2 p1 = u2f2(acc2[i][1]);
        float2 p2 = u2f2(acc2[i][2]);
        float2 p3 = u2f2(acc2[i][3]);
        v.x = elu_f(p0.x + p0.y + sb[f0 + 0]);
        v.y = elu_f(p1.x + p1.y + sb[f0 + 1]);
        v.z = elu_f(p2.x + p2.y + sb[f0 + 2]);
        v.w = elu_f(p3.x + p3.y + sb[f0 + 3]);
        *(float4*)(sax + (r0 + i) * SAX_STRIDE + f0) = v;
    }
    __syncthreads();

    // epilogue: t9p = y2@W3l (padded rows), xr9 = y2@W3r
    {
        int err2 = tid & 127;
        int m = tid >> 7;
        int grow = row0 + err2;
        const float* yrow = sax + err2 * SAX_STRIDE;
        const unsigned long long* w3p = (const unsigned long long*)sW3 + m * 288;
        unsigned long long o2[9];
        #pragma unroll
        for (int f = 0; f < 9; f++) o2[f] = 0ull;
        #pragma unroll 4
        for (int k2 = 0; k2 < 32; k2++) {
            unsigned long long y2p = *(const unsigned long long*)(yrow + 2 * k2);
            const unsigned long long* wk = w3p + k2 * 9;
            #pragma unroll
            for (int f = 0; f < 9; f++) ffma2(o2[f], y2p, wk[f]);
        }
        if (grow < ROWS) {
            float* dst = m ? (g_xr9all + ((long)t * ROWS + grow) * 9)
                           : (g_t9pall + ((long)t * ROWS + grow) * 16);
            #pragma unroll
            for (int f = 0; f < 9; f++) { float2 p = u2f2(o2[f]); dst[f] = p.x + p.y; }
        }
    }
}

// ============================================================================
// y9: ALL timesteps of sage3 aggregation + elu.
// ============================================================================
__global__ void __launch_bounds__(256) y9_kernel(const float* __restrict__ b3)
{
    int tid = threadIdx.x;
    int warp = tid >> 5, lane = tid & 31;
    int hh = lane >> 4, f16 = lane & 15;
    int fb = f16 * 4;

    int t    = blockIdx.x / Y9_TILES;
    int tile = blockIdx.x % Y9_TILES;
    int row0 = tile * 256;

    float b3v = (f16 < 9) ? b3[t * 9 + f16] : 0.f;
    const char* tball = (const char*)(g_t9pall + (long)t * ROWS * 16);
    const float* xrall = g_xr9all + (long)t * ROWS * 9;
    float* y9t = g_y9all + (long)t * ROWS * 16;

    #pragma unroll 1
    for (int pass = 0; pass < 4; pass++) {
        int rbase = warp * 32 + hh * 16 + pass * 4;
        float acc[4];
        const char* tb[4];
        int sA[4], eA[4], nn_[4];
        int maxlen = 0;
        #pragma unroll
        for (int i = 0; i < 4; i++) {
            int row = row0 + rbase + i;
            acc[i] = 0.f;
            if (row < ROWS) {
                int b = row / NN, n = row % NN;
                nn_[i] = n;
                tb[i] = tball + (long)b * NN * 64;
                sA[i] = g_ptr[n]; eA[i] = g_ptr[n + 1];
                int len = eA[i] - sA[i];
                maxlen = len > maxlen ? len : maxlen;
            } else { nn_[i] = -1; tb[i] = tball; sA[i] = 0; eA[i] = 0; }
        }
        for (int k = 0; k < maxlen; k++) {
            #pragma unroll
            for (int i = 0; i < 4; i++) {
                int j = sA[i] + k;
                if (j < eA[i]) {
                    int2 sw = g_csr_sw[j];
                    float v = *(const float*)(tb[i] + sw.x + fb);
                    acc[i] = fmaf(__int_as_float(sw.y), v, acc[i]);
                }
            }
        }
        #pragma unroll
        for (int i = 0; i < 4; i++) {
            if (nn_[i] >= 0) {
                int row = row0 + rbase + i;
                float val = 0.f;
                if (f16 < 9)
                    val = elu_f(acc[i] + xrall[(long)row * 9 + f16] + b3v);
                y9t[(long)row * 16 + f16] = val;
            }
        }
    }
}

// ============================================================================
// gru_all: all 12 GRU steps; h in registers; writes collapsed output.
// ============================================================================
__global__ void __launch_bounds__(256) gru_all_kernel(
    const float* __restrict__ Wih, const float* __restrict__ Whh,
    const float* __restrict__ bih, const float* __restrict__ bhh,
    float* __restrict__ out)
{
    __shared__ float swih[TT * 243], swhh[TT * 243];
    __shared__ float sbi[TT * 27], sbh[TT * 27];
    __shared__ float sv9[9], svc[BB];

    int tid = threadIdx.x;
    for (int i = tid; i < TT * 243; i += 256) { swih[i] = Wih[i]; swhh[i] = Whh[i]; }
    for (int i = tid; i < TT * 27; i += 256) { sbi[i] = bih[i]; sbh[i] = bhh[i]; }
    if (tid < 9) sv9[tid] = g_v[tid];
    if (tid < BB) svc[tid] = g_vc[tid];
    __syncthreads();

    int idx = blockIdx.x * 256 + tid;
    if (idx >= ROWS) return;
    int b = idx / NN, n = idx % NN;

    float h[9];
    #pragma unroll
    for (int f = 0; f < 9; f++) h[f] = 0.f;

    #pragma unroll 1
    for (int t = 0; t < TT; t++) {
        const float* yp = g_y9all + ((long)t * ROWS + idx) * 16;
        float y[9];
        float4 y0 = *(const float4*)yp;
        float4 y1 = *(const float4*)(yp + 4);
        y[0] = y0.x; y[1] = y0.y; y[2] = y0.z; y[3] = y0.w;
        y[4] = y1.x; y[5] = y1.y; y[6] = y1.z; y[7] = y1.w;
        y[8] = yp[8];

        const float* wiT = swih + t * 243;
        const float* whT = swhh + t * 243;
        const float* biT = sbi + t * 27;
        const float* bhT = sbh + t * 27;

        float gs[18], gin[9], ghn[9];
        #pragma unroll
        for (int j = 0; j < 18; j++) gs[j] = biT[j] + bhT[j];
        #pragma unroll
        for (int j = 0; j < 9; j++) { gin[j] = biT[18 + j]; ghn[j] = bhT[18 + j]; }
        #pragma unroll
        for (int k = 0; k < 9; k++) {
            float yk = y[k], hk = h[k];
            const float* wi = wiT + k * 27;
            const float* wh = whT + k * 27;
            #pragma unroll
            for (int j = 0; j < 18; j++) gs[j] = fmaf(yk, wi[j], fmaf(hk, wh[j], gs[j]));
            #pragma unroll
            for (int j = 0; j < 9; j++) {
                gin[j] = fmaf(yk, wi[18 + j], gin[j]);
                ghn[j] = fmaf(hk, wh[18 + j], ghn[j]);
            }
        }

        long iout = ((long)b * TT + t) * NN + n;
        float dot = svc[b];
        #pragma unroll
        for (int f = 0; f < 9; f++) {
            float r  = 1.f / (1.f + expf(-gs[f]));
            float z  = 1.f / (1.f + expf(-gs[9 + f]));
            float nv = tanhf(gin[f] + r * ghn[f]);
            float hv = (1.f - z) * nv + z * h[f];
            h[f] = hv;
            dot = fmaf(hv, sv9[f], dot);
        }
        float mask = g_x16[iout * 16];
        out[iout] = (mask != 0.f) ? dot : 0.f;
    }
}

// ---------------- host ------------------------------------------------------
extern "C" void kernel_launch(void* const* d_in, const int* in_sizes, int n_in,
                              void* d_out, int out_size) {
    const float* graph = (const float*)d_in[0];
    const float* tev   = (const float*)d_in[1];
    const float* ew    = (const float*)d_in[3];
    const int*   esrc  = (const int*)d_in[4];
    const int*   edst  = (const int*)d_in[5];
    const float* W1l = (const float*)d_in[6];
    const float* b1  = (const float*)d_in[7];
    const float* W1r = (const float*)d_in[8];
    const float* W2l = (const float*)d_in[9];
    const float* b2  = (const float*)d_in[10];
    const float* W2r = (const float*)d_in[11];
    const float* W3l = (const float*)d_in[12];
    const float* b3  = (const float*)d_in[13];
    const float* W3r = (const float*)d_in[14];
    const float* Wih = (const float*)d_in[15];
    const float* Whh = (const float*)d_in[16];
    const float* bih = (const float*)d_in[17];
    const float* bhh = (const float*)d_in[18];
    const float* encW = (const float*)d_in[19];
    const float* encb = (const float*)d_in[20];
    const float* decW = (const float*)d_in[21];
    const float* decb = (const float*)d_in[22];
    float* out = (float*)d_out;

    cudaFuncSetAttribute(big_lin64_kernel,
                         cudaFuncAttributeMaxDynamicSharedMemorySize, SM64_BYTES);

    prep_scan_kernel<<<PREP_BLOCKS, 256>>>(graph, edst, encW, encb, decW, decb, tev);
    fill_kernel<<<(EE + 255) / 256, 256>>>(esrc, edst, ew);
    big_lin9_kernel<<<TT * L9_TILES, 256>>>(W1l, W1r, b1);
    big_lin64_kernel<<<TT * K1_TILES, 256, SM64_BYTES>>>(W2l, W2r, b2, W3l, W3r);
    y9_kernel<<<TT * Y9_TILES, 256>>>(b3);
    gru_all_kernel<<<(ROWS + 255) / 256, 256>>>(Wih, Whh, bih, bhh, out);
}

// round 13
// speedup vs baseline: 1.2396x; 1.0837x over previous
#include <cuda_runtime.h>
#include <math.h>

#define NN   20000
#define BB   2
#define TT   12
#define FIN  9
#define HH   64
#define EE   200000
#define ROWS (BB*NN)   // 40000

#define L9_TILES   313    // 128 rows each
#define K64_TILES  625    // 64 rows each (lin64)
#define Y9_TILES   157    // 256 rows each
#define XROWS      (BB * TT * NN)   // 480000
#define PREP_BLOCKS (XROWS / 256)   // 1875

// ---------------- scratch (device globals; no allocations allowed) ----------
__device__ int   g_cnt[NN];
__device__ int   g_fill[NN];
__device__ int   g_ptr[NN + 1];
__device__ float g_deginv[NN];
__device__ unsigned int g_ticket;
__device__ int2  g_csr_sw[EE];     // (src, f2i(w * deginv[dst]))
__device__ __align__(16) float g_y1all[(long)TT * ROWS * HH];
__device__ __align__(16) float g_t9pall[(long)TT * ROWS * 16];
__device__ __align__(16) float g_xr9all[(long)TT * ROWS * FIN];
__device__ __align__(16) float g_y9all[(long)TT * ROWS * 16];
__device__ __align__(16) float g_x16[(long)XROWS * 16];
__device__ float g_v[9];
__device__ float g_vc[BB];

// ---------------- helpers ----------------------------------------------------
__device__ __forceinline__ float elu_f(float v) { return v > 0.f ? v : expm1f(v); }

__device__ __forceinline__ void ffma2(unsigned long long& d,
                                      unsigned long long a, unsigned long long b) {
    asm("fma.rn.f32x2 %0, %1, %2, %0;" : "+l"(d) : "l"(a), "l"(b));
}
__device__ __forceinline__ float2 u2f2(unsigned long long u) {
    float2 r; asm("mov.b64 {%0, %1}, %2;" : "=f"(r.x), "=f"(r.y) : "l"(u)); return r;
}

// ---------------- prep+scan (last-block ticket) -------------------------------
__global__ void __launch_bounds__(256) prep_scan_kernel(
    const float* __restrict__ graph, const int* __restrict__ edst,
    const float* __restrict__ encW, const float* __restrict__ encb,
    const float* __restrict__ decW, const float* __restrict__ decb,
    const float* __restrict__ tev)
{
    int tid = threadIdx.x;
    int i = blockIdx.x * 256 + tid;
    if (i < XROWS) {
        float v[16];
        #pragma unroll
        for (int f = 0; f < 16; f++) v[f] = 0.f;
        const float* gp = graph + (long)i * 9;
        #pragma unroll
        for (int f = 0; f < 9; f++) v[f] = gp[f];
        float4* dst = (float4*)(g_x16 + (long)i * 16);
        dst[0] = make_float4(v[0], v[1], v[2], v[3]);
        dst[1] = make_float4(v[4], v[5], v[6], v[7]);
        dst[2] = make_float4(v[8], v[9], v[10], v[11]);
        dst[3] = make_float4(v[12], v[13], v[14], v[15]);
    }
    if (i < EE) atomicAdd(&g_cnt[edst[i]], 1);
    __threadfence();

    __shared__ unsigned int slast;
    if (tid == 0) slast = atomicAdd(&g_ticket, 1u);
    __syncthreads();
    if (slast != (unsigned)(gridDim.x - 1)) return;
    if (tid == 0) g_ticket = 0;

    __shared__ float sv[19];
    if (tid < 18) {
        float s = 0.f;
        for (int j = 0; j < 64; j++) s = fmaf(encW[tid * 64 + j], decW[j], s);
        sv[tid] = s;
    } else if (tid == 18) {
        float s = decb[0];
        for (int j = 0; j < 64; j++) s = fmaf(encb[j], decW[j], s);
        sv[18] = s;
    }
    __syncthreads();
    if (tid < 9) g_v[tid] = sv[tid];
    if (tid < BB) {
        float c = sv[18];
        #pragma unroll
        for (int f = 0; f < 9; f++) c = fmaf(tev[tid * 9 + f], sv[9 + f], c);
        g_vc[tid] = c;
    }

    __shared__ int wsum[8];
    __shared__ int carry;
    int lane = tid & 31, wid = tid >> 5;
    if (tid == 0) { carry = 0; g_ptr[0] = 0; }
    __syncthreads();
    for (int base = 0; base < NN; base += 256) {
        int idx = base + tid;
        int v = (idx < NN) ? __ldcg(&g_cnt[idx]) : 0;
        if (idx < NN) {
            g_deginv[idx] = 1.0f / fmaxf((float)v, 1.0f);
            g_cnt[idx] = 0;
            g_fill[idx] = 0;
        }
        int s = v;
        #pragma unroll
        for (int off = 1; off < 32; off <<= 1) {
            int tv = __shfl_up_sync(0xffffffffu, s, off);
            if (lane >= off) s += tv;
        }
        if (lane == 31) wsum[wid] = s;
        __syncthreads();
        if (wid == 0) {
            int ws = (lane < 8) ? wsum[lane] : 0;
            #pragma unroll
            for (int off = 1; off < 8; off <<= 1) {
                int tv = __shfl_up_sync(0xffffffffu, ws, off, 8);
                if ((lane & 7) >= off) ws += tv;
            }
            if (lane < 8) wsum[lane] = ws;
        }
        __syncthreads();
        int excl = wid ? wsum[wid - 1] : 0;
        if (idx < NN) g_ptr[idx + 1] = carry + excl + s;
        __syncthreads();
        if (tid == 0) carry += wsum[7];
        __syncthreads();
    }
}

__global__ void fill_kernel(const int* __restrict__ src, const int* __restrict__ dst,
                            const float* __restrict__ w) {
    int e = blockIdx.x * 256 + threadIdx.x;
    if (e < EE) {
        int d = dst[e];
        int pos = g_ptr[d] + atomicAdd(&g_fill[d], 1);
        g_csr_sw[pos] = make_int2(src[e], __float_as_int(w[e] * g_deginv[d]));
    }
}

// ============================================================================
// big_lin9: ALL timesteps of sage1. 128 rows/block, GEMM 4 rows x 8 cols.
// ============================================================================
__global__ void __launch_bounds__(256) big_lin9_kernel(
    const float* __restrict__ W1l, const float* __restrict__ W1r,
    const float* __restrict__ b1)
{
    __shared__ __align__(16) float sW9[18 * 64];
    __shared__ __align__(16) float sb9[64];
    __shared__ float sax9[128 * 33];

    int tid = threadIdx.x;
    int warp = tid >> 5, lane = tid & 31;
    int hh = lane >> 4, f16 = lane & 15;

    int t  = blockIdx.x / L9_TILES;
    int lb = blockIdx.x % L9_TILES;
    int row0 = lb * 128;

    const float* w1l = W1l + t * 576;
    const float* w1r = W1r + t * 576;
    for (int i = tid; i < 1152; i += 256)
        sW9[i] = (i < 576) ? w1l[i] : w1r[i - 576];
    if (tid < 64) sb9[tid] = b1[t * 64 + tid];

    #pragma unroll 1
    for (int pass = 0; pass < 2; pass++) {
        int rbase = (warp * 2 + hh) * 8 + pass * 4;
        float acc[4];
        const float* xb[4];
        int sA[4], eA[4], nn_[4];
        int maxlen = 0;
        #pragma unroll
        for (int i = 0; i < 4; i++) {
            int row = row0 + rbase + i;
            acc[i] = 0.f;
            if (row < ROWS) {
                int b = row / NN, n = row % NN;
                nn_[i] = n;
                xb[i] = g_x16 + ((long)b * TT + t) * NN * 16;
                sA[i] = g_ptr[n]; eA[i] = g_ptr[n + 1];
                int len = eA[i] - sA[i];
                maxlen = len > maxlen ? len : maxlen;
            } else { nn_[i] = -1; xb[i] = g_x16; sA[i] = 0; eA[i] = 0; }
        }
        for (int k = 0; k < maxlen; k++) {
            #pragma unroll
            for (int i = 0; i < 4; i++) {
                int j = sA[i] + k;
                if (j < eA[i]) {
                    int2 sw = g_csr_sw[j];
                    acc[i] = fmaf(__int_as_float(sw.y),
                                  xb[i][(long)sw.x * 16 + f16], acc[i]);
                }
            }
        }
        #pragma unroll
        for (int i = 0; i < 4; i++) {
            if (nn_[i] >= 0) {
                int rr = rbase + i;
                sax9[rr * 33 + f16] = acc[i];
                sax9[rr * 33 + 16 + f16] = xb[i][(long)nn_[i] * 16 + f16];
            }
        }
    }
    __syncthreads();

    int cx = tid & 7, ry = tid >> 3;
    int f0 = cx * 8, r0 = ry * 4;
    float4 accA[4], accB[4];
    {
        float4 bA = *(const float4*)&sb9[f0];
        float4 bB = *(const float4*)&sb9[f0 + 4];
        #pragma unroll
        for (int i = 0; i < 4; i++) { accA[i] = bA; accB[i] = bB; }
    }
    #pragma unroll
    for (int k = 0; k < 18; k++) {
        float4 w0 = *(const float4*)&sW9[k * 64 + f0];
        float4 w1 = *(const float4*)&sW9[k * 64 + f0 + 4];
        int ko = (k < 9) ? k : (k + 7);
        #pragma unroll
        for (int i = 0; i < 4; i++) {
            float a = sax9[(r0 + i) * 33 + ko];
            accA[i].x = fmaf(a, w0.x, accA[i].x);
            accA[i].y = fmaf(a, w0.y, accA[i].y);
            accA[i].z = fmaf(a, w0.z, accA[i].z);
            accA[i].w = fmaf(a, w0.w, accA[i].w);
            accB[i].x = fmaf(a, w1.x, accB[i].x);
            accB[i].y = fmaf(a, w1.y, accB[i].y);
            accB[i].z = fmaf(a, w1.z, accB[i].z);
            accB[i].w = fmaf(a, w1.w, accB[i].w);
        }
    }
    float* ybase = g_y1all + (long)t * ROWS * 64;
    #pragma unroll
    for (int i = 0; i < 4; i++) {
        int row = row0 + r0 + i;
        if (row < ROWS) {
            float4 vA = accA[i], vB = accB[i];
            vA.x = elu_f(vA.x); vA.y = elu_f(vA.y); vA.z = elu_f(vA.z); vA.w = elu_f(vA.w);
            vB.x = elu_f(vB.x); vB.y = elu_f(vB.y); vB.z = elu_f(vB.z); vB.w = elu_f(vB.w);
            *(float4*)(ybase + (long)row * 64 + f0) = vA;
            *(float4*)(ybase + (long)row * 64 + f0 + 4) = vB;
        }
    }
}

// ============================================================================
// big_lin64: 64-row tiles, 3 blocks/SM (24 warps). Fused gather + ffma2 GEMM
// (4 rows x 4 cols) + elu + W3 epilogue.
// ============================================================================
#define SAX_STRIDE 132
#define SM64_FLOATS (8192 + 1152 + 64 + 64 * SAX_STRIDE)
#define SM64_BYTES  (SM64_FLOATS * 4)     // 71424 B -> 3 blocks/SM

__global__ void __launch_bounds__(256, 3) big_lin64_kernel(
    const float* __restrict__ W2l_, const float* __restrict__ W2r_,
    const float* __restrict__ b2_,
    const float* __restrict__ W3l_, const float* __restrict__ W3r_)
{
    extern __shared__ __align__(16) float sm[];
    float* sW2 = sm;                 // [64 k-pairs][64 f][2]
    float* sW3 = sW2 + 8192;         // [2 m][32 k-pairs][9 f][2]
    float* sb  = sW3 + 1152;         // [64]
    float* sax = sb + 64;            // [64][132]: 0..63 agg | 64..127 x

    int t    = blockIdx.x / K64_TILES;
    int tile = blockIdx.x % K64_TILES;
    const float* W2l = W2l_ + t * 4096;
    const float* W2r = W2r_ + t * 4096;
    const float* b2  = b2_  + t * 64;
    const float* W3l = W3l_ + t * 576;
    const float* W3r = W3r_ + t * 576;

    int tid = threadIdx.x;
    for (int i = tid; i < 8192; i += 256) {
        int f = i & 63, kk = i >> 6;
        float v = (kk < 64) ? W2l[kk * 64 + f] : W2r[(kk - 64) * 64 + f];
        sW2[((kk >> 1) * 64 + f) * 2 + (kk & 1)] = v;
    }
    for (int i = tid; i < 1152; i += 256) {
        int m = (i >= 576);
        int rem = i - m * 576;
        int kk = rem / 9, f = rem % 9;
        float v = m ? W3r[kk * 9 + f] : W3l[kk * 9 + f];
        sW3[m * 576 + ((kk >> 1) * 9 + f) * 2 + (kk & 1)] = v;
    }
    if (tid < 64) sb[tid] = b2[tid];

    int row0 = tile * 64;
    int warp = tid >> 5, lane = tid & 31;
    const float* ytbase = g_y1all + (long)t * ROWS * 64;

    // gather: 8 rows per warp; 2 passes of 4 rows in flight, lane owns 2 feats
    #pragma unroll 1
    for (int pass = 0; pass < 2; pass++) {
        int rbase = warp * 8 + pass * 4;
        float2 acc[4];
        const float* yb[4];
        int sA[4], eA[4], nn_[4];
        int maxlen = 0;
        #pragma unroll
        for (int i = 0; i < 4; i++) {
            int row = row0 + rbase + i;
            acc[i] = make_float2(0.f, 0.f);
            if (row < ROWS) {
                int b = row / NN, n = row % NN;
                nn_[i] = n;
                yb[i] = ytbase + (long)b * NN * 64;
                sA[i] = g_ptr[n]; eA[i] = g_ptr[n + 1];
                int len = eA[i] - sA[i];
                maxlen = len > maxlen ? len : maxlen;
            } else { nn_[i] = -1; yb[i] = ytbase; sA[i] = 0; eA[i] = 0; }
        }
        for (int k = 0; k < maxlen; k++) {
            #pragma unroll
            for (int i = 0; i < 4; i++) {
                int j = sA[i] + k;
                if (j < eA[i]) {
                    int2 sw = g_csr_sw[j];
                    float2 v = *(const float2*)(yb[i] + (long)sw.x * 64 + lane * 2);
                    float wt = __int_as_float(sw.y);
                    acc[i].x = fmaf(wt, v.x, acc[i].x);
                    acc[i].y = fmaf(wt, v.y, acc[i].y);
                }
            }
        }
        #pragma unroll
        for (int i = 0; i < 4; i++) {
            if (nn_[i] >= 0) {
                int rr = rbase + i;
                *(float2*)(sax + rr * SAX_STRIDE + lane * 2) = acc[i];
                *(float2*)(sax + rr * SAX_STRIDE + 64 + lane * 2) =
                    *(const float2*)(yb[i] + (long)nn_[i] * 64 + lane * 2);
            }
        }
    }
    __syncthreads();

    // GEMM: 4 rows x 4 cols per thread, K=128 as 64 f32x2 pairs
    int tx = tid & 15, ty = tid >> 4;
    int f0 = tx * 4, r0 = ty * 4;
    unsigned long long acc2[4][4];
    #pragma unroll
    for (int i = 0; i < 4; i++)
        #pragma unroll
        for (int j = 0; j < 4; j++) acc2[i][j] = 0ull;

    const unsigned long long* w2 = (const unsigned long long*)sW2;
    #pragma unroll 2
    for (int k2 = 0; k2 < 64; k2++) {
        const unsigned long long* wp = w2 + (k2 * 64 + f0);
        ulonglong2 wa = *(const ulonglong2*)(wp);
        ulonglong2 wb = *(const ulonglong2*)(wp + 2);
        #pragma unroll
        for (int i = 0; i < 4; i++) {
            unsigned long long a2 =
                *(const unsigned long long*)(sax + (r0 + i) * SAX_STRIDE + 2 * k2);
            ffma2(acc2[i][0], a2, wa.x);
            ffma2(acc2[i][1], a2, wa.y);
            ffma2(acc2[i][2], a2, wb.x);
            ffma2(acc2[i][3], a2, wb.y);
        }
    }
    __syncthreads();

    #pragma unroll
    for (int i = 0; i < 4; i++) {
        float4 v;
        float2 p0 = u2f2(acc2[i][0]);
        float2 p1 = u2f2(acc2[i][1]);
        float2 p2 = u2f2(acc2[i][2]);
        float2 p3 = u2f2(acc2[i][3]);
        v.x = elu_f(p0.x + p0.y + sb[f0 + 0]);
        v.y = elu_f(p1.x + p1.y + sb[f0 + 1]);
        v.z = elu_f(p2.x + p2.y + sb[f0 + 2]);
        v.w = elu_f(p3.x + p3.y + sb[f0 + 3]);
        *(float4*)(sax + (r0 + i) * SAX_STRIDE + f0) = v;
    }
    __syncthreads();

    // epilogue (threads 0..127): t9p = y2@W3l, xr9 = y2@W3r
    if (tid < 128) {
        int err2 = tid & 63;
        int m = tid >> 6;
        int grow = row0 + err2;
        const float* yrow = sax + err2 * SAX_STRIDE;
        const unsigned long long* w3p = (const unsigned long long*)sW3 + m * 288;
        unsigned long long o2[9];
        #pragma unroll
        for (int f = 0; f < 9; f++) o2[f] = 0ull;
        #pragma unroll 4
        for (int k2 = 0; k2 < 32; k2++) {
            unsigned long long y2p = *(const unsigned long long*)(yrow + 2 * k2);
            const unsigned long long* wk = w3p + k2 * 9;
            #pragma unroll
            for (int f = 0; f < 9; f++) ffma2(o2[f], y2p, wk[f]);
        }
        if (grow < ROWS) {
            float* dst = m ? (g_xr9all + ((long)t * ROWS + grow) * 9)
                           : (g_t9pall + ((long)t * ROWS + grow) * 16);
            #pragma unroll
            for (int f = 0; f < 9; f++) { float2 p = u2f2(o2[f]); dst[f] = p.x + p.y; }
        }
    }
}

// ============================================================================
// y9: ALL timesteps of sage3 aggregation + elu.
// ============================================================================
__global__ void __launch_bounds__(256) y9_kernel(const float* __restrict__ b3)
{
    int tid = threadIdx.x;
    int warp = tid >> 5, lane = tid & 31;
    int hh = lane >> 4, f16 = lane & 15;

    int t    = blockIdx.x / Y9_TILES;
    int tile = blockIdx.x % Y9_TILES;
    int row0 = tile * 256;

    float b3v = (f16 < 9) ? b3[t * 9 + f16] : 0.f;
    const float* tball = g_t9pall + (long)t * ROWS * 16;
    const float* xrall = g_xr9all + (long)t * ROWS * 9;
    float* y9t = g_y9all + (long)t * ROWS * 16;

    #pragma unroll 1
    for (int pass = 0; pass < 4; pass++) {
        int rbase = warp * 32 + hh * 16 + pass * 4;
        float acc[4];
        const float* tb[4];
        int sA[4], eA[4], nn_[4];
        int maxlen = 0;
        #pragma unroll
        for (int i = 0; i < 4; i++) {
            int row = row0 + rbase + i;
            acc[i] = 0.f;
            if (row < ROWS) {
                int b = row / NN, n = row % NN;
                nn_[i] = n;
                tb[i] = tball + (long)b * NN * 16;
                sA[i] = g_ptr[n]; eA[i] = g_ptr[n + 1];
                int len = eA[i] - sA[i];
                maxlen = len > maxlen ? len : maxlen;
            } else { nn_[i] = -1; tb[i] = tball; sA[i] = 0; eA[i] = 0; }
        }
        for (int k = 0; k < maxlen; k++) {
            #pragma unroll
            for (int i = 0; i < 4; i++) {
                int j = sA[i] + k;
                if (j < eA[i]) {
                    int2 sw = g_csr_sw[j];
                    acc[i] = fmaf(__int_as_float(sw.y),
                                  tb[i][(long)sw.x * 16 + f16], acc[i]);
                }
            }
        }
        #pragma unroll
        for (int i = 0; i < 4; i++) {
            if (nn_[i] >= 0) {
                int row = row0 + rbase + i;
                float val = 0.f;
                if (f16 < 9)
                    val = elu_f(acc[i] + xrall[(long)row * 9 + f16] + b3v);
                y9t[(long)row * 16 + f16] = val;
            }
        }
    }
}

// ============================================================================
// gru_all: all 12 GRU steps; h in registers; writes collapsed output.
// ============================================================================
__global__ void __launch_bounds__(256) gru_all_kernel(
    const float* __restrict__ Wih, const float* __restrict__ Whh,
    const float* __restrict__ bih, const float* __restrict__ bhh,
    float* __restrict__ out)
{
    __shared__ float swih[TT * 243], swhh[TT * 243];
    __shared__ float sbi[TT * 27], sbh[TT * 27];
    __shared__ float sv9[9], svc[BB];

    int tid = threadIdx.x;
    for (int i = tid; i < TT * 243; i += 256) { swih[i] = Wih[i]; swhh[i] = Whh[i]; }
    for (int i = tid; i < TT * 27; i += 256) { sbi[i] = bih[i]; sbh[i] = bhh[i]; }
    if (tid < 9) sv9[tid] = g_v[tid];
    if (tid < BB) svc[tid] = g_vc[tid];
    __syncthreads();

    int idx = blockIdx.x * 256 + tid;
    if (idx >= ROWS) return;
    int b = idx / NN, n = idx % NN;

    float h[9];
    #pragma unroll
    for (int f = 0; f < 9; f++) h[f] = 0.f;

    #pragma unroll 1
    for (int t = 0; t < TT; t++) {
        const float* yp = g_y9all + ((long)t * ROWS + idx) * 16;
        float y[9];
        float4 y0 = *(const float4*)yp;
        float4 y1 = *(const float4*)(yp + 4);
        y[0] = y0.x; y[1] = y0.y; y[2] = y0.z; y[3] = y0.w;
        y[4] = y1.x; y[5] = y1.y; y[6] = y1.z; y[7] = y1.w;
        y[8] = yp[8];

        const float* wiT = swih + t * 243;
        const float* whT = swhh + t * 243;
        const float* biT = sbi + t * 27;
        const float* bhT = sbh + t * 27;

        float gs[18], gin[9], ghn[9];
        #pragma unroll
        for (int j = 0; j < 18; j++) gs[j] = biT[j] + bhT[j];
        #pragma unroll
        for (int j = 0; j < 9; j++) { gin[j] = biT[18 + j]; ghn[j] = bhT[18 + j]; }
        #pragma unroll
        for (int k = 0; k < 9; k++) {
            float yk = y[k], hk = h[k];
            const float* wi = wiT + k * 27;
            const float* wh = whT + k * 27;
            #pragma unroll
            for (int j = 0; j < 18; j++) gs[j] = fmaf(yk, wi[j], fmaf(hk, wh[j], gs[j]));
            #pragma unroll
            for (int j = 0; j < 9; j++) {
                gin[j] = fmaf(yk, wi[18 + j], gin[j]);
                ghn[j] = fmaf(hk, wh[18 + j], ghn[j]);
            }
        }

        long iout = ((long)b * TT + t) * NN + n;
        float dot = svc[b];
        #pragma unroll
        for (int f = 0; f < 9; f++) {
            float r  = 1.f / (1.f + expf(-gs[f]));
            float z  = 1.f / (1.f + expf(-gs[9 + f]));
            float nv = tanhf(gin[f] + r * ghn[f]);
            float hv = (1.f - z) * nv + z * h[f];
            h[f] = hv;
            dot = fmaf(hv, sv9[f], dot);
        }
        float mask = g_x16[iout * 16];
        out[iout] = (mask != 0.f) ? dot : 0.f;
    }
}

// ---------------- host ------------------------------------------------------
extern "C" void kernel_launch(void* const* d_in, const int* in_sizes, int n_in,
                              void* d_out, int out_size) {
    const float* graph = (const float*)d_in[0];
    const float* tev   = (const float*)d_in[1];
    const float* ew    = (const float*)d_in[3];
    const int*   esrc  = (const int*)d_in[4];
    const int*   edst  = (const int*)d_in[5];
    const float* W1l = (const float*)d_in[6];
    const float* b1  = (const float*)d_in[7];
    const float* W1r = (const float*)d_in[8];
    const float* W2l = (const float*)d_in[9];
    const float* b2  = (const float*)d_in[10];
    const float* W2r = (const float*)d_in[11];
    const float* W3l = (const float*)d_in[12];
    const float* b3  = (const float*)d_in[13];
    const float* W3r = (const float*)d_in[14];
    const float* Wih = (const float*)d_in[15];
    const float* Whh = (const float*)d_in[16];
    const float* bih = (const float*)d_in[17];
    const float* bhh = (const float*)d_in[18];
    const float* encW = (const float*)d_in[19];
    const float* encb = (const float*)d_in[20];
    const float* decW = (const float*)d_in[21];
    const float* decb = (const float*)d_in[22];
    float* out = (float*)d_out;

    cudaFuncSetAttribute(big_lin64_kernel,
                         cudaFuncAttributeMaxDynamicSharedMemorySize, SM64_BYTES);

    prep_scan_kernel<<<PREP_BLOCKS, 256>>>(graph, edst, encW, encb, decW, decb, tev);
    fill_kernel<<<(EE + 255) / 256, 256>>>(esrc, edst, ew);
    big_lin9_kernel<<<TT * L9_TILES, 256>>>(W1l, W1r, b1);
    big_lin64_kernel<<<TT * K64_TILES, 256, SM64_BYTES>>>(W2l, W2r, b2, W3l, W3r);
    y9_kernel<<<TT * Y9_TILES, 256>>>(b3);
    gru_all_kernel<<<(ROWS + 255) / 256, 256>>>(Wih, Whh, bih, bhh, out);
}